// round 13
// baseline (speedup 1.0000x reference)
#include <cuda_runtime.h>
#include <mma.h>
#include <math.h>
#include <stdint.h>

using namespace nvcuda;

#define T_TOKENS 65536
#define D_MODEL  256
#define E_EXPERTS 8
#define F_FF     1024
#define CAP      10240

// ---------------- scratch (ONLY the R1/R10/R11-proven globals) ----------------
__device__ __align__(128) float g_buf[(size_t)E_EXPERTS * CAP * D_MODEL];
__device__ __align__(128) float g_hmid[(size_t)E_EXPERTS * CAP * F_FF];
__device__ int   g_idx[T_TOKENS];
__device__ float g_prb[T_TOKENS];
__device__ int   g_slot_token[E_EXPERTS * CAP];
__device__ float g_slot_prob[E_EXPERTS * CAP];
__device__ int   g_count[E_EXPERTS];

__device__ __forceinline__ void tsplit(float v, float& h, float& l) {
    h = wmma::__float_to_tf32(v);
    l = wmma::__float_to_tf32(v - h);
}

// SMEM padded strides
#define ALD 20    // A ldm (floats): 2-way max conflict
#define BLD 132   // B ldm (floats): 132 % 32 == 4 -> conflict-free 8-row frags

// ---------------- prep kernels (verbatim from passing rounds) -----------------
__global__ void zero_kernel(float4* __restrict__ out, int n4) {
    int i = blockIdx.x * blockDim.x + threadIdx.x;
    if (i < n4) out[i] = make_float4(0.f, 0.f, 0.f, 0.f);
}

__global__ void gate_kernel(const float* __restrict__ x,
                            const float* __restrict__ gw,
                            const float* __restrict__ gb) {
    __shared__ float s_gw[D_MODEL * E_EXPERTS];
    int tid = threadIdx.x;
    for (int i = tid; i < D_MODEL * E_EXPERTS; i += 256) s_gw[i] = gw[i];
    __syncthreads();
    int warp = tid >> 5, lane = tid & 31;
    int t = blockIdx.x * 8 + warp;
    const float* xr = x + (size_t)t * D_MODEL;
    float acc[E_EXPERTS];
#pragma unroll
    for (int e = 0; e < E_EXPERTS; e++) acc[e] = 0.f;
#pragma unroll
    for (int j = 0; j < 8; j++) {
        int d = j * 32 + lane;
        float xv = xr[d];
#pragma unroll
        for (int e = 0; e < E_EXPERTS; e++) acc[e] += xv * s_gw[d * E_EXPERTS + e];
    }
#pragma unroll
    for (int o = 16; o > 0; o >>= 1)
#pragma unroll
        for (int e = 0; e < E_EXPERTS; e++)
            acc[e] += __shfl_xor_sync(0xffffffffu, acc[e], o);
    if (lane == 0) {
        float lg[E_EXPERTS], m = -INFINITY; int am = 0;
#pragma unroll
        for (int e = 0; e < E_EXPERTS; e++) {
            lg[e] = acc[e] + gb[e];
            if (lg[e] > m) { m = lg[e]; am = e; }
        }
        float s = 0.f;
#pragma unroll
        for (int e = 0; e < E_EXPERTS; e++) s += expf(lg[e] - m);
        g_idx[t] = am;
        g_prb[t] = 1.0f / s;
    }
}

__global__ void scan_kernel() {
    __shared__ int s[1024][E_EXPERTS];
    int tid = threadIdx.x;
    int base = tid * (T_TOKENS / 1024);
    int cnt[E_EXPERTS];
#pragma unroll
    for (int e = 0; e < E_EXPERTS; e++) cnt[e] = 0;
    for (int i = 0; i < T_TOKENS / 1024; i++) cnt[g_idx[base + i]]++;
#pragma unroll
    for (int e = 0; e < E_EXPERTS; e++) s[tid][e] = cnt[e];
    __syncthreads();
    for (int off = 1; off < 1024; off <<= 1) {
        int v[E_EXPERTS];
        if (tid >= off)
#pragma unroll
            for (int e = 0; e < E_EXPERTS; e++) v[e] = s[tid - off][e];
        __syncthreads();
        if (tid >= off)
#pragma unroll
            for (int e = 0; e < E_EXPERTS; e++) s[tid][e] += v[e];
        __syncthreads();
    }
    int run[E_EXPERTS];
#pragma unroll
    for (int e = 0; e < E_EXPERTS; e++) run[e] = s[tid][e] - cnt[e];
    if (tid == 1023)
#pragma unroll
        for (int e = 0; e < E_EXPERTS; e++) g_count[e] = min(s[1023][e], CAP);
    for (int i = 0; i < T_TOKENS / 1024; i++) {
        int t = base + i;
        int e = g_idx[t];
        int pos = run[e]++;
        if (pos < CAP) {
            int slot = e * CAP + pos;
            g_slot_token[slot] = t;
            g_slot_prob[slot]  = g_prb[t];
        }
    }
}

__global__ void dispatch_kernel(const float* __restrict__ x) {
    int slot = blockIdx.x * 4 + (threadIdx.x >> 6);
    int e = slot / CAP, c = slot % CAP;
    if (c >= g_count[e]) return;
    int t = g_slot_token[slot];
    int i = threadIdx.x & 63;
    const float4* src = (const float4*)(x + (size_t)t * D_MODEL);
    float4* dst = (float4*)(g_buf + (size_t)slot * D_MODEL);
    dst[i] = src[i];
}

// ---------------- tf32 WMMA mainloop with in-kernel conversion ----------------
// CTA 128m x 128n, 8 warps (2m x 4n), warp 64x32 = 4x2 m16n16k8 frags, K-chunk 16.
// A source fp32 [rows][astr], B source fp32 [k][bstr] (already offset to n0).
template <int KTOT>
__device__ __forceinline__ void tf32_mainloop(
        float (*sAh)[ALD], float (*sAl)[ALD],
        float (*sBh)[BLD], float (*sBl)[BLD],
        const float* __restrict__ A, int astr,
        const float* __restrict__ B, int bstr,
        wmma::fragment<wmma::accumulator, 16, 16, 8, float> acc[4][2],
        int wm, int wn) {
    int tid = threadIdx.x;
    int arow = tid >> 1, acol = (tid & 1) * 8;
    int brow = tid >> 4, bcol = (tid & 15) * 8;

#pragma unroll 1
    for (int k0 = 0; k0 < KTOT; k0 += 16) {
        float4 a0 = *(const float4*)(A + (size_t)arow * astr + k0 + acol);
        float4 a1 = *(const float4*)(A + (size_t)arow * astr + k0 + acol + 4);
        float4 h0, l0, h1, l1;
        tsplit(a0.x, h0.x, l0.x); tsplit(a0.y, h0.y, l0.y);
        tsplit(a0.z, h0.z, l0.z); tsplit(a0.w, h0.w, l0.w);
        tsplit(a1.x, h1.x, l1.x); tsplit(a1.y, h1.y, l1.y);
        tsplit(a1.z, h1.z, l1.z); tsplit(a1.w, h1.w, l1.w);
        *(float4*)(&sAh[arow][acol])     = h0;
        *(float4*)(&sAh[arow][acol + 4]) = h1;
        *(float4*)(&sAl[arow][acol])     = l0;
        *(float4*)(&sAl[arow][acol + 4]) = l1;

        float4 b0 = *(const float4*)(B + (size_t)(k0 + brow) * bstr + bcol);
        float4 b1v = *(const float4*)(B + (size_t)(k0 + brow) * bstr + bcol + 4);
        float4 bh0, bl0, bh1, bl1;
        tsplit(b0.x, bh0.x, bl0.x); tsplit(b0.y, bh0.y, bl0.y);
        tsplit(b0.z, bh0.z, bl0.z); tsplit(b0.w, bh0.w, bl0.w);
        tsplit(b1v.x, bh1.x, bl1.x); tsplit(b1v.y, bh1.y, bl1.y);
        tsplit(b1v.z, bh1.z, bl1.z); tsplit(b1v.w, bh1.w, bl1.w);
        *(float4*)(&sBh[brow][bcol])     = bh0;
        *(float4*)(&sBh[brow][bcol + 4]) = bh1;
        *(float4*)(&sBl[brow][bcol])     = bl0;
        *(float4*)(&sBl[brow][bcol + 4]) = bl1;
        __syncthreads();

#pragma unroll
        for (int ks = 0; ks < 2; ks++) {
            wmma::fragment<wmma::matrix_a, 16, 16, 8, wmma::precision::tf32, wmma::row_major> ah[4], al[4];
            wmma::fragment<wmma::matrix_b, 16, 16, 8, wmma::precision::tf32, wmma::row_major> bh[2], bl[2];
#pragma unroll
            for (int mi = 0; mi < 4; mi++) {
                wmma::load_matrix_sync(ah[mi], &sAh[wm + mi * 16][ks * 8], ALD);
                wmma::load_matrix_sync(al[mi], &sAl[wm + mi * 16][ks * 8], ALD);
            }
#pragma unroll
            for (int ni = 0; ni < 2; ni++) {
                wmma::load_matrix_sync(bh[ni], &sBh[ks * 8][wn + ni * 16], BLD);
                wmma::load_matrix_sync(bl[ni], &sBl[ks * 8][wn + ni * 16], BLD);
            }
#pragma unroll
            for (int mi = 0; mi < 4; mi++)
#pragma unroll
                for (int ni = 0; ni < 2; ni++) {
                    wmma::mma_sync(acc[mi][ni], ah[mi], bh[ni], acc[mi][ni]);
                    wmma::mma_sync(acc[mi][ni], ah[mi], bl[ni], acc[mi][ni]);
                    wmma::mma_sync(acc[mi][ni], al[mi], bh[ni], acc[mi][ni]);
                }
        }
        __syncthreads();
    }
}

// ---------------- GEMM1: hmid = relu(buf @ w1 + b1), fp32 out -----------------
__global__ __launch_bounds__(256) void gemm1_wmma(const float* __restrict__ w1,
                                                  const float* __restrict__ b1) {
    __shared__ float sAh[128][ALD], sAl[128][ALD];
    __shared__ float sBh[16][BLD], sBl[16][BLD];
    __shared__ __align__(32) float sbuf[8][256];

    int e = blockIdx.z, m0 = blockIdx.y * 128, n0 = blockIdx.x * 128;
    if (m0 >= g_count[e]) return;
    int tid = threadIdx.x, wid = tid >> 5, lane = tid & 31;
    int wm = (wid >> 2) * 64, wn = (wid & 3) * 32;

    wmma::fragment<wmma::accumulator, 16, 16, 8, float> acc[4][2];
#pragma unroll
    for (int mi = 0; mi < 4; mi++)
#pragma unroll
        for (int ni = 0; ni < 2; ni++) wmma::fill_fragment(acc[mi][ni], 0.f);

    tf32_mainloop<D_MODEL>(sAh, sAl, sBh, sBl,
        g_buf + (size_t)(e * CAP + m0) * D_MODEL, D_MODEL,
        w1 + (size_t)e * D_MODEL * F_FF + n0, F_FF,
        acc, wm, wn);

    const float* bb = b1 + e * F_FF + n0 + wn;
    int r = lane >> 1, cb = (lane & 1) * 8;
#pragma unroll
    for (int mi = 0; mi < 4; mi++)
#pragma unroll
        for (int ni = 0; ni < 2; ni++) {
            wmma::store_matrix_sync(&sbuf[wid][0], acc[mi][ni], 16, wmma::mem_row_major);
            __syncwarp();
            float* hr = g_hmid + (size_t)(e * CAP + m0 + wm + mi * 16 + r) * F_FF
                        + n0 + wn + ni * 16 + cb;
#pragma unroll
            for (int j = 0; j < 8; j++) {
                float v = sbuf[wid][r * 16 + cb + j] + __ldg(bb + ni * 16 + cb + j);
                hr[j] = fmaxf(v, 0.f);
            }
            __syncwarp();
        }
}

// ---------------- GEMM2: y[token] = (hmid @ w2 + b2) * prob -------------------
__global__ __launch_bounds__(256) void gemm2_wmma(const float* __restrict__ w2,
                                                  const float* __restrict__ b2,
                                                  float* __restrict__ y) {
    __shared__ float sAh[128][ALD], sAl[128][ALD];
    __shared__ float sBh[16][BLD], sBl[16][BLD];
    __shared__ __align__(32) float sbuf[8][256];

    int e = blockIdx.z, m0 = blockIdx.y * 128, n0 = blockIdx.x * 128;
    int cnt = g_count[e];
    if (m0 >= cnt) return;
    int tid = threadIdx.x, wid = tid >> 5, lane = tid & 31;
    int wm = (wid >> 2) * 64, wn = (wid & 3) * 32;

    wmma::fragment<wmma::accumulator, 16, 16, 8, float> acc[4][2];
#pragma unroll
    for (int mi = 0; mi < 4; mi++)
#pragma unroll
        for (int ni = 0; ni < 2; ni++) wmma::fill_fragment(acc[mi][ni], 0.f);

    tf32_mainloop<F_FF>(sAh, sAl, sBh, sBl,
        g_hmid + (size_t)(e * CAP + m0) * F_FF, F_FF,
        w2 + (size_t)e * F_FF * D_MODEL + n0, D_MODEL,
        acc, wm, wn);

    const float* bb = b2 + e * D_MODEL + n0 + wn;
    int r = lane >> 1, cb = (lane & 1) * 8;
#pragma unroll
    for (int mi = 0; mi < 4; mi++)
#pragma unroll
        for (int ni = 0; ni < 2; ni++) {
            wmma::store_matrix_sync(&sbuf[wid][0], acc[mi][ni], 16, wmma::mem_row_major);
            __syncwarp();
            int row = m0 + wm + mi * 16 + r;
            if (row < cnt) {
                int t = g_slot_token[e * CAP + row];
                float p = g_slot_prob[e * CAP + row];
                float* yr = y + (size_t)t * D_MODEL + n0 + wn + ni * 16 + cb;
#pragma unroll
                for (int j = 0; j < 8; j += 2) {
                    float2 v;
                    v.x = (sbuf[wid][r * 16 + cb + j]     + __ldg(bb + ni * 16 + cb + j))     * p;
                    v.y = (sbuf[wid][r * 16 + cb + j + 1] + __ldg(bb + ni * 16 + cb + j + 1)) * p;
                    *(float2*)(yr + j) = v;
                }
            }
            __syncwarp();
        }
}

// ---------------- launch -------------------------------------------------------
extern "C" void kernel_launch(void* const* d_in, const int* in_sizes, int n_in,
                              void* d_out, int out_size) {
    const float* h      = (const float*)d_in[0];
    const float* gate_w = (const float*)d_in[1];
    const float* gate_b = (const float*)d_in[2];
    const float* w1     = (const float*)d_in[3];
    const float* b1     = (const float*)d_in[4];
    const float* w2     = (const float*)d_in[5];
    const float* b2     = (const float*)d_in[6];
    float* out = (float*)d_out;

    int n4 = out_size / 4;
    zero_kernel<<<(n4 + 255) / 256, 256>>>((float4*)out, n4);
    gate_kernel<<<T_TOKENS / 8, 256>>>(h, gate_w, gate_b);
    scan_kernel<<<1, 1024>>>();
    dispatch_kernel<<<E_EXPERTS * CAP / 4, 256>>>(h);
    gemm1_wmma<<<dim3(F_FF / 128, CAP / 128, E_EXPERTS), 256>>>(w1, b1);
    gemm2_wmma<<<dim3(D_MODEL / 128, CAP / 128, E_EXPERTS), 256>>>(w2, b2, out);
}

// round 14
// speedup vs baseline: 2.7281x; 2.7281x over previous
#include <cuda_runtime.h>
#include <cuda_fp16.h>
#include <mma.h>
#include <math.h>
#include <stdint.h>

using namespace nvcuda;

#define T_TOKENS 65536
#define D_MODEL  256
#define E_EXPERTS 8
#define F_FF     1024
#define CAP      10240

// ---------------- scratch (ONLY proven globals) -------------------------------
__device__ __align__(128) float g_buf[(size_t)E_EXPERTS * CAP * D_MODEL];
__device__ __align__(128) float g_hmid[(size_t)E_EXPERTS * CAP * F_FF];
__device__ int   g_idx[T_TOKENS];
__device__ float g_prb[T_TOKENS];
__device__ int   g_slot_token[E_EXPERTS * CAP];
__device__ float g_slot_prob[E_EXPERTS * CAP];
__device__ int   g_count[E_EXPERTS];

// pack 2 floats -> half2 hi (returned) + half2 lo (out param)
__device__ __forceinline__ uint32_t packh2(float v0, float v1, uint32_t& lo) {
    __half h0 = __float2half_rn(v0), h1 = __float2half_rn(v1);
    __half l0 = __float2half_rn(v0 - __half2float(h0));
    __half l1 = __float2half_rn(v1 - __half2float(h1));
    __half2 hh = __halves2half2(h0, h1);
    __half2 ll = __halves2half2(l0, l1);
    lo = *(uint32_t*)&ll;
    return *(uint32_t*)&hh;
}

// SMEM strides (in halfs)
#define ALD 40    // 128x32 A tile + 8 pad
#define BLD 136   // 32x128 B tile + 8 pad

// ---------------- prep kernels (verbatim from passing rounds) -----------------
__global__ void zero_kernel(float4* __restrict__ out, int n4) {
    int i = blockIdx.x * blockDim.x + threadIdx.x;
    if (i < n4) out[i] = make_float4(0.f, 0.f, 0.f, 0.f);
}

__global__ void gate_kernel(const float* __restrict__ x,
                            const float* __restrict__ gw,
                            const float* __restrict__ gb) {
    __shared__ float s_gw[D_MODEL * E_EXPERTS];
    int tid = threadIdx.x;
    for (int i = tid; i < D_MODEL * E_EXPERTS; i += 256) s_gw[i] = gw[i];
    __syncthreads();
    int warp = tid >> 5, lane = tid & 31;
    int t = blockIdx.x * 8 + warp;
    const float* xr = x + (size_t)t * D_MODEL;
    float acc[E_EXPERTS];
#pragma unroll
    for (int e = 0; e < E_EXPERTS; e++) acc[e] = 0.f;
#pragma unroll
    for (int j = 0; j < 8; j++) {
        int d = j * 32 + lane;
        float xv = xr[d];
#pragma unroll
        for (int e = 0; e < E_EXPERTS; e++) acc[e] += xv * s_gw[d * E_EXPERTS + e];
    }
#pragma unroll
    for (int o = 16; o > 0; o >>= 1)
#pragma unroll
        for (int e = 0; e < E_EXPERTS; e++)
            acc[e] += __shfl_xor_sync(0xffffffffu, acc[e], o);
    if (lane == 0) {
        float lg[E_EXPERTS], m = -INFINITY; int am = 0;
#pragma unroll
        for (int e = 0; e < E_EXPERTS; e++) {
            lg[e] = acc[e] + gb[e];
            if (lg[e] > m) { m = lg[e]; am = e; }
        }
        float s = 0.f;
#pragma unroll
        for (int e = 0; e < E_EXPERTS; e++) s += expf(lg[e] - m);
        g_idx[t] = am;
        g_prb[t] = 1.0f / s;
    }
}

__global__ void scan_kernel() {
    __shared__ int s[1024][E_EXPERTS];
    int tid = threadIdx.x;
    int base = tid * (T_TOKENS / 1024);
    int cnt[E_EXPERTS];
#pragma unroll
    for (int e = 0; e < E_EXPERTS; e++) cnt[e] = 0;
    for (int i = 0; i < T_TOKENS / 1024; i++) cnt[g_idx[base + i]]++;
#pragma unroll
    for (int e = 0; e < E_EXPERTS; e++) s[tid][e] = cnt[e];
    __syncthreads();
    for (int off = 1; off < 1024; off <<= 1) {
        int v[E_EXPERTS];
        if (tid >= off)
#pragma unroll
            for (int e = 0; e < E_EXPERTS; e++) v[e] = s[tid - off][e];
        __syncthreads();
        if (tid >= off)
#pragma unroll
            for (int e = 0; e < E_EXPERTS; e++) s[tid][e] += v[e];
        __syncthreads();
    }
    int run[E_EXPERTS];
#pragma unroll
    for (int e = 0; e < E_EXPERTS; e++) run[e] = s[tid][e] - cnt[e];
    if (tid == 1023)
#pragma unroll
        for (int e = 0; e < E_EXPERTS; e++) g_count[e] = min(s[1023][e], CAP);
    for (int i = 0; i < T_TOKENS / 1024; i++) {
        int t = base + i;
        int e = g_idx[t];
        int pos = run[e]++;
        if (pos < CAP) {
            int slot = e * CAP + pos;
            g_slot_token[slot] = t;
            g_slot_prob[slot]  = g_prb[t];
        }
    }
}

__global__ void dispatch_kernel(const float* __restrict__ x) {
    int slot = blockIdx.x * 4 + (threadIdx.x >> 6);
    int e = slot / CAP, c = slot % CAP;
    if (c >= g_count[e]) return;
    int t = g_slot_token[slot];
    int i = threadIdx.x & 63;
    const float4* src = (const float4*)(x + (size_t)t * D_MODEL);
    float4* dst = (float4*)(g_buf + (size_t)slot * D_MODEL);
    dst[i] = src[i];
}

// ---------------- fp16 3-term WMMA mainloop (in-kernel conversion) ------------
// CTA 128m x 128n, 8 warps (2m x 4n), warp 64x32 = 4x2 m16n16k16 frags, K-chunk 32.
template <int KTOT>
__device__ __forceinline__ void fp16_mainloop(
        __half (*sAh)[ALD], __half (*sAl)[ALD],
        __half (*sBh)[BLD], __half (*sBl)[BLD],
        const float* __restrict__ A, int astr,
        const float* __restrict__ B, int bstr,
        wmma::fragment<wmma::accumulator, 16, 16, 16, float> acc[4][2],
        int wm, int wn) {
    int tid = threadIdx.x;
    int arow = tid >> 1, acol = (tid & 1) * 16;
    int brow = tid >> 3, bcol = (tid & 7) * 16;

#pragma unroll 1
    for (int k0 = 0; k0 < KTOT; k0 += 32) {
        {
            const float* Ap = A + (size_t)arow * astr + k0 + acol;
            float4 a0 = *(const float4*)(Ap);
            float4 a1 = *(const float4*)(Ap + 4);
            float4 a2 = *(const float4*)(Ap + 8);
            float4 a3 = *(const float4*)(Ap + 12);
            uint4 h0, l0, h1, l1;
            h0.x = packh2(a0.x, a0.y, l0.x); h0.y = packh2(a0.z, a0.w, l0.y);
            h0.z = packh2(a1.x, a1.y, l0.z); h0.w = packh2(a1.z, a1.w, l0.w);
            h1.x = packh2(a2.x, a2.y, l1.x); h1.y = packh2(a2.z, a2.w, l1.y);
            h1.z = packh2(a3.x, a3.y, l1.z); h1.w = packh2(a3.z, a3.w, l1.w);
            *(uint4*)(&sAh[arow][acol])     = h0;
            *(uint4*)(&sAh[arow][acol + 8]) = h1;
            *(uint4*)(&sAl[arow][acol])     = l0;
            *(uint4*)(&sAl[arow][acol + 8]) = l1;
        }
        {
            const float* Bp = B + (size_t)(k0 + brow) * bstr + bcol;
            float4 b0 = *(const float4*)(Bp);
            float4 b1 = *(const float4*)(Bp + 4);
            float4 b2 = *(const float4*)(Bp + 8);
            float4 b3 = *(const float4*)(Bp + 12);
            uint4 h0, l0, h1, l1;
            h0.x = packh2(b0.x, b0.y, l0.x); h0.y = packh2(b0.z, b0.w, l0.y);
            h0.z = packh2(b1.x, b1.y, l0.z); h0.w = packh2(b1.z, b1.w, l0.w);
            h1.x = packh2(b2.x, b2.y, l1.x); h1.y = packh2(b2.z, b2.w, l1.y);
            h1.z = packh2(b3.x, b3.y, l1.z); h1.w = packh2(b3.z, b3.w, l1.w);
            *(uint4*)(&sBh[brow][bcol])     = h0;
            *(uint4*)(&sBh[brow][bcol + 8]) = h1;
            *(uint4*)(&sBl[brow][bcol])     = l0;
            *(uint4*)(&sBl[brow][bcol + 8]) = l1;
        }
        __syncthreads();

#pragma unroll
        for (int ks = 0; ks < 2; ks++) {
            wmma::fragment<wmma::matrix_a, 16, 16, 16, __half, wmma::row_major> ah[4], al[4];
            wmma::fragment<wmma::matrix_b, 16, 16, 16, __half, wmma::row_major> bh[2], bl[2];
#pragma unroll
            for (int mi = 0; mi < 4; mi++) {
                wmma::load_matrix_sync(ah[mi], &sAh[wm + mi * 16][ks * 16], ALD);
                wmma::load_matrix_sync(al[mi], &sAl[wm + mi * 16][ks * 16], ALD);
            }
#pragma unroll
            for (int ni = 0; ni < 2; ni++) {
                wmma::load_matrix_sync(bh[ni], &sBh[ks * 16][wn + ni * 16], BLD);
                wmma::load_matrix_sync(bl[ni], &sBl[ks * 16][wn + ni * 16], BLD);
            }
#pragma unroll
            for (int mi = 0; mi < 4; mi++)
#pragma unroll
                for (int ni = 0; ni < 2; ni++) {
                    wmma::mma_sync(acc[mi][ni], ah[mi], bh[ni], acc[mi][ni]);
                    wmma::mma_sync(acc[mi][ni], ah[mi], bl[ni], acc[mi][ni]);
                    wmma::mma_sync(acc[mi][ni], al[mi], bh[ni], acc[mi][ni]);
                }
        }
        __syncthreads();
    }
}

// ---------------- GEMM1: hmid = relu(buf @ w1 + b1), fp32 out -----------------
__global__ __launch_bounds__(256) void gemm1_wmma(const float* __restrict__ w1,
                                                  const float* __restrict__ b1) {
    __shared__ __half sAh[128][ALD], sAl[128][ALD];
    __shared__ __half sBh[32][BLD], sBl[32][BLD];
    __shared__ __align__(32) float sbuf[8][256];

    int e = blockIdx.z, m0 = blockIdx.y * 128, n0 = blockIdx.x * 128;
    if (m0 >= g_count[e]) return;
    int tid = threadIdx.x, wid = tid >> 5, lane = tid & 31;
    int wm = (wid >> 2) * 64, wn = (wid & 3) * 32;

    wmma::fragment<wmma::accumulator, 16, 16, 16, float> acc[4][2];
#pragma unroll
    for (int mi = 0; mi < 4; mi++)
#pragma unroll
        for (int ni = 0; ni < 2; ni++) wmma::fill_fragment(acc[mi][ni], 0.f);

    fp16_mainloop<D_MODEL>(sAh, sAl, sBh, sBl,
        g_buf + (size_t)(e * CAP + m0) * D_MODEL, D_MODEL,
        w1 + (size_t)e * D_MODEL * F_FF + n0, F_FF,
        acc, wm, wn);

    const float* bb = b1 + e * F_FF + n0 + wn;
    int r = lane >> 1, cb = (lane & 1) * 8;
#pragma unroll
    for (int mi = 0; mi < 4; mi++)
#pragma unroll
        for (int ni = 0; ni < 2; ni++) {
            wmma::store_matrix_sync(&sbuf[wid][0], acc[mi][ni], 16, wmma::mem_row_major);
            __syncwarp();
            float* hr = g_hmid + (size_t)(e * CAP + m0 + wm + mi * 16 + r) * F_FF
                        + n0 + wn + ni * 16 + cb;
#pragma unroll
            for (int j = 0; j < 8; j++) {
                float v = sbuf[wid][r * 16 + cb + j] + __ldg(bb + ni * 16 + cb + j);
                hr[j] = fmaxf(v, 0.f);
            }
            __syncwarp();
        }
}

// ---------------- GEMM2: y[token] = (hmid @ w2 + b2) * prob -------------------
__global__ __launch_bounds__(256) void gemm2_wmma(const float* __restrict__ w2,
                                                  const float* __restrict__ b2,
                                                  float* __restrict__ y) {
    __shared__ __half sAh[128][ALD], sAl[128][ALD];
    __shared__ __half sBh[32][BLD], sBl[32][BLD];
    __shared__ __align__(32) float sbuf[8][256];

    int e = blockIdx.z, m0 = blockIdx.y * 128, n0 = blockIdx.x * 128;
    int cnt = g_count[e];
    if (m0 >= cnt) return;
    int tid = threadIdx.x, wid = tid >> 5, lane = tid & 31;
    int wm = (wid >> 2) * 64, wn = (wid & 3) * 32;

    wmma::fragment<wmma::accumulator, 16, 16, 16, float> acc[4][2];
#pragma unroll
    for (int mi = 0; mi < 4; mi++)
#pragma unroll
        for (int ni = 0; ni < 2; ni++) wmma::fill_fragment(acc[mi][ni], 0.f);

    fp16_mainloop<F_FF>(sAh, sAl, sBh, sBl,
        g_hmid + (size_t)(e * CAP + m0) * F_FF, F_FF,
        w2 + (size_t)e * F_FF * D_MODEL + n0, D_MODEL,
        acc, wm, wn);

    const float* bb = b2 + e * D_MODEL + n0 + wn;
    int r = lane >> 1, cb = (lane & 1) * 8;
#pragma unroll
    for (int mi = 0; mi < 4; mi++)
#pragma unroll
        for (int ni = 0; ni < 2; ni++) {
            wmma::store_matrix_sync(&sbuf[wid][0], acc[mi][ni], 16, wmma::mem_row_major);
            __syncwarp();
            int row = m0 + wm + mi * 16 + r;
            if (row < cnt) {
                int t = g_slot_token[e * CAP + row];
                float p = g_slot_prob[e * CAP + row];
                float* yr = y + (size_t)t * D_MODEL + n0 + wn + ni * 16 + cb;
#pragma unroll
                for (int j = 0; j < 8; j += 2) {
                    float2 v;
                    v.x = (sbuf[wid][r * 16 + cb + j]     + __ldg(bb + ni * 16 + cb + j))     * p;
                    v.y = (sbuf[wid][r * 16 + cb + j + 1] + __ldg(bb + ni * 16 + cb + j + 1)) * p;
                    *(float2*)(yr + j) = v;
                }
            }
            __syncwarp();
        }
}

// ---------------- launch -------------------------------------------------------
extern "C" void kernel_launch(void* const* d_in, const int* in_sizes, int n_in,
                              void* d_out, int out_size) {
    const float* h      = (const float*)d_in[0];
    const float* gate_w = (const float*)d_in[1];
    const float* gate_b = (const float*)d_in[2];
    const float* w1     = (const float*)d_in[3];
    const float* b1     = (const float*)d_in[4];
    const float* w2     = (const float*)d_in[5];
    const float* b2     = (const float*)d_in[6];
    float* out = (float*)d_out;

    int n4 = out_size / 4;
    zero_kernel<<<(n4 + 255) / 256, 256>>>((float4*)out, n4);
    gate_kernel<<<T_TOKENS / 8, 256>>>(h, gate_w, gate_b);
    scan_kernel<<<1, 1024>>>();
    dispatch_kernel<<<E_EXPERTS * CAP / 4, 256>>>(h);
    gemm1_wmma<<<dim3(F_FF / 128, CAP / 128, E_EXPERTS), 256>>>(w1, b1);
    gemm2_wmma<<<dim3(D_MODEL / 128, CAP / 128, E_EXPERTS), 256>>>(w2, b2, out);
}

// round 15
// speedup vs baseline: 3.1479x; 1.1539x over previous
#include <cuda_runtime.h>
#include <cuda_fp16.h>
#include <mma.h>
#include <math.h>
#include <stdint.h>

using namespace nvcuda;

#define T_TOKENS 65536
#define D_MODEL  256
#define E_EXPERTS 8
#define F_FF     1024
#define CAP      10240

// ---------------- scratch (ONLY proven globals) -------------------------------
__device__ __align__(128) float g_buf[(size_t)E_EXPERTS * CAP * D_MODEL];
__device__ __align__(128) float g_hmid[(size_t)E_EXPERTS * CAP * F_FF];
__device__ int   g_idx[T_TOKENS];
__device__ float g_prb[T_TOKENS];
__device__ int   g_slot_token[E_EXPERTS * CAP];
__device__ float g_slot_prob[E_EXPERTS * CAP];
__device__ int   g_count[E_EXPERTS];

// pack 2 floats -> half2 hi (returned) + half2 lo (out param) — half2 fast path
__device__ __forceinline__ uint32_t packh2(float v0, float v1, uint32_t& lo) {
    __half2 hh = __float22half2_rn(make_float2(v0, v1));
    float2 bk = __half22float2(hh);
    __half2 ll = __float22half2_rn(make_float2(v0 - bk.x, v1 - bk.y));
    lo = *(uint32_t*)&ll;
    return *(uint32_t*)&hh;
}

// SMEM strides (in halfs)
#define ALD 40    // 128x32 A tile + 8 pad
#define BLD 136   // 32x128 B tile + 8 pad

// ---------------- prep kernels (verbatim from passing rounds) -----------------
__global__ void zero_kernel(float4* __restrict__ out, int n4) {
    int i = blockIdx.x * blockDim.x + threadIdx.x;
    if (i < n4) out[i] = make_float4(0.f, 0.f, 0.f, 0.f);
}

__global__ void gate_kernel(const float* __restrict__ x,
                            const float* __restrict__ gw,
                            const float* __restrict__ gb) {
    __shared__ float s_gw[D_MODEL * E_EXPERTS];
    int tid = threadIdx.x;
    for (int i = tid; i < D_MODEL * E_EXPERTS; i += 256) s_gw[i] = gw[i];
    __syncthreads();
    int warp = tid >> 5, lane = tid & 31;
    int t = blockIdx.x * 8 + warp;
    const float* xr = x + (size_t)t * D_MODEL;
    float acc[E_EXPERTS];
#pragma unroll
    for (int e = 0; e < E_EXPERTS; e++) acc[e] = 0.f;
#pragma unroll
    for (int j = 0; j < 8; j++) {
        int d = j * 32 + lane;
        float xv = xr[d];
#pragma unroll
        for (int e = 0; e < E_EXPERTS; e++) acc[e] += xv * s_gw[d * E_EXPERTS + e];
    }
#pragma unroll
    for (int o = 16; o > 0; o >>= 1)
#pragma unroll
        for (int e = 0; e < E_EXPERTS; e++)
            acc[e] += __shfl_xor_sync(0xffffffffu, acc[e], o);
    if (lane == 0) {
        float lg[E_EXPERTS], m = -INFINITY; int am = 0;
#pragma unroll
        for (int e = 0; e < E_EXPERTS; e++) {
            lg[e] = acc[e] + gb[e];
            if (lg[e] > m) { m = lg[e]; am = e; }
        }
        float s = 0.f;
#pragma unroll
        for (int e = 0; e < E_EXPERTS; e++) s += expf(lg[e] - m);
        g_idx[t] = am;
        g_prb[t] = 1.0f / s;
    }
}

__global__ void scan_kernel() {
    __shared__ int s[1024][E_EXPERTS];
    int tid = threadIdx.x;
    int base = tid * (T_TOKENS / 1024);
    int cnt[E_EXPERTS];
#pragma unroll
    for (int e = 0; e < E_EXPERTS; e++) cnt[e] = 0;
    for (int i = 0; i < T_TOKENS / 1024; i++) cnt[g_idx[base + i]]++;
#pragma unroll
    for (int e = 0; e < E_EXPERTS; e++) s[tid][e] = cnt[e];
    __syncthreads();
    for (int off = 1; off < 1024; off <<= 1) {
        int v[E_EXPERTS];
        if (tid >= off)
#pragma unroll
            for (int e = 0; e < E_EXPERTS; e++) v[e] = s[tid - off][e];
        __syncthreads();
        if (tid >= off)
#pragma unroll
            for (int e = 0; e < E_EXPERTS; e++) s[tid][e] += v[e];
        __syncthreads();
    }
    int run[E_EXPERTS];
#pragma unroll
    for (int e = 0; e < E_EXPERTS; e++) run[e] = s[tid][e] - cnt[e];
    if (tid == 1023)
#pragma unroll
        for (int e = 0; e < E_EXPERTS; e++) g_count[e] = min(s[1023][e], CAP);
    for (int i = 0; i < T_TOKENS / 1024; i++) {
        int t = base + i;
        int e = g_idx[t];
        int pos = run[e]++;
        if (pos < CAP) {
            int slot = e * CAP + pos;
            g_slot_token[slot] = t;
            g_slot_prob[slot]  = g_prb[t];
        }
    }
}

__global__ void dispatch_kernel(const float* __restrict__ x) {
    int slot = blockIdx.x * 4 + (threadIdx.x >> 6);
    int e = slot / CAP, c = slot % CAP;
    if (c >= g_count[e]) return;
    int t = g_slot_token[slot];
    int i = threadIdx.x & 63;
    const float4* src = (const float4*)(x + (size_t)t * D_MODEL);
    float4* dst = (float4*)(g_buf + (size_t)slot * D_MODEL);
    dst[i] = src[i];
}

// ---------------- fp16 3-term WMMA mainloop (prefetch + fast convert) ---------
// CTA 128m x 128n, 8 warps (2m x 4n), warp 64x32 = 4x2 m16n16k16 frags, K-chunk 32.
template <int KTOT>
__device__ __forceinline__ void fp16_mainloop(
        __half (*sAh)[ALD], __half (*sAl)[ALD],
        __half (*sBh)[BLD], __half (*sBl)[BLD],
        const float* __restrict__ A, int astr,
        const float* __restrict__ B, int bstr,
        wmma::fragment<wmma::accumulator, 16, 16, 16, float> acc[4][2],
        int wm, int wn) {
    int tid = threadIdx.x;
    int arow = tid >> 1, acol = (tid & 1) * 16;
    int brow = tid >> 3, bcol = (tid & 7) * 16;

    float4 pa[4], pb[4];
    auto ldchunk = [&](int k0) {
        const float* Ap = A + (size_t)arow * astr + k0 + acol;
        pa[0] = *(const float4*)(Ap);
        pa[1] = *(const float4*)(Ap + 4);
        pa[2] = *(const float4*)(Ap + 8);
        pa[3] = *(const float4*)(Ap + 12);
        const float* Bp = B + (size_t)(k0 + brow) * bstr + bcol;
        pb[0] = *(const float4*)(Bp);
        pb[1] = *(const float4*)(Bp + 4);
        pb[2] = *(const float4*)(Bp + 8);
        pb[3] = *(const float4*)(Bp + 12);
    };

    ldchunk(0);

#pragma unroll 1
    for (int k0 = 0; k0 < KTOT; k0 += 32) {
        // convert prefetched regs -> smem
        {
            uint4 h0, l0, h1, l1;
            h0.x = packh2(pa[0].x, pa[0].y, l0.x); h0.y = packh2(pa[0].z, pa[0].w, l0.y);
            h0.z = packh2(pa[1].x, pa[1].y, l0.z); h0.w = packh2(pa[1].z, pa[1].w, l0.w);
            h1.x = packh2(pa[2].x, pa[2].y, l1.x); h1.y = packh2(pa[2].z, pa[2].w, l1.y);
            h1.z = packh2(pa[3].x, pa[3].y, l1.z); h1.w = packh2(pa[3].z, pa[3].w, l1.w);
            *(uint4*)(&sAh[arow][acol])     = h0;
            *(uint4*)(&sAh[arow][acol + 8]) = h1;
            *(uint4*)(&sAl[arow][acol])     = l0;
            *(uint4*)(&sAl[arow][acol + 8]) = l1;
        }
        {
            uint4 h0, l0, h1, l1;
            h0.x = packh2(pb[0].x, pb[0].y, l0.x); h0.y = packh2(pb[0].z, pb[0].w, l0.y);
            h0.z = packh2(pb[1].x, pb[1].y, l0.z); h0.w = packh2(pb[1].z, pb[1].w, l0.w);
            h1.x = packh2(pb[2].x, pb[2].y, l1.x); h1.y = packh2(pb[2].z, pb[2].w, l1.y);
            h1.z = packh2(pb[3].x, pb[3].y, l1.z); h1.w = packh2(pb[3].z, pb[3].w, l1.w);
            *(uint4*)(&sBh[brow][bcol])     = h0;
            *(uint4*)(&sBh[brow][bcol + 8]) = h1;
            *(uint4*)(&sBl[brow][bcol])     = l0;
            *(uint4*)(&sBl[brow][bcol + 8]) = l1;
        }
        __syncthreads();

        // issue next chunk's global loads (latency hidden behind MMA)
        if (k0 + 32 < KTOT) ldchunk(k0 + 32);

#pragma unroll
        for (int ks = 0; ks < 2; ks++) {
            wmma::fragment<wmma::matrix_a, 16, 16, 16, __half, wmma::row_major> ah[4], al[4];
            wmma::fragment<wmma::matrix_b, 16, 16, 16, __half, wmma::row_major> bh[2], bl[2];
#pragma unroll
            for (int mi = 0; mi < 4; mi++) {
                wmma::load_matrix_sync(ah[mi], &sAh[wm + mi * 16][ks * 16], ALD);
                wmma::load_matrix_sync(al[mi], &sAl[wm + mi * 16][ks * 16], ALD);
            }
#pragma unroll
            for (int ni = 0; ni < 2; ni++) {
                wmma::load_matrix_sync(bh[ni], &sBh[ks * 16][wn + ni * 16], BLD);
                wmma::load_matrix_sync(bl[ni], &sBl[ks * 16][wn + ni * 16], BLD);
            }
#pragma unroll
            for (int mi = 0; mi < 4; mi++)
#pragma unroll
                for (int ni = 0; ni < 2; ni++) {
                    wmma::mma_sync(acc[mi][ni], ah[mi], bh[ni], acc[mi][ni]);
                    wmma::mma_sync(acc[mi][ni], ah[mi], bl[ni], acc[mi][ni]);
                    wmma::mma_sync(acc[mi][ni], al[mi], bh[ni], acc[mi][ni]);
                }
        }
        __syncthreads();
    }
}

// ---------------- GEMM1: hmid = relu(buf @ w1 + b1), fp32 out -----------------
__global__ __launch_bounds__(256) void gemm1_wmma(const float* __restrict__ w1,
                                                  const float* __restrict__ b1) {
    __shared__ __half sAh[128][ALD], sAl[128][ALD];
    __shared__ __half sBh[32][BLD], sBl[32][BLD];
    __shared__ __align__(32) float sbuf[8][256];

    int e = blockIdx.z, m0 = blockIdx.y * 128, n0 = blockIdx.x * 128;
    if (m0 >= g_count[e]) return;
    int tid = threadIdx.x, wid = tid >> 5, lane = tid & 31;
    int wm = (wid >> 2) * 64, wn = (wid & 3) * 32;

    wmma::fragment<wmma::accumulator, 16, 16, 16, float> acc[4][2];
#pragma unroll
    for (int mi = 0; mi < 4; mi++)
#pragma unroll
        for (int ni = 0; ni < 2; ni++) wmma::fill_fragment(acc[mi][ni], 0.f);

    fp16_mainloop<D_MODEL>(sAh, sAl, sBh, sBl,
        g_buf + (size_t)(e * CAP + m0) * D_MODEL, D_MODEL,
        w1 + (size_t)e * D_MODEL * F_FF + n0, F_FF,
        acc, wm, wn);

    const float* bb = b1 + e * F_FF + n0 + wn;
    int r = lane >> 1, cb = (lane & 1) * 8;
#pragma unroll
    for (int mi = 0; mi < 4; mi++)
#pragma unroll
        for (int ni = 0; ni < 2; ni++) {
            wmma::store_matrix_sync(&sbuf[wid][0], acc[mi][ni], 16, wmma::mem_row_major);
            __syncwarp();
            float* hr = g_hmid + (size_t)(e * CAP + m0 + wm + mi * 16 + r) * F_FF
                        + n0 + wn + ni * 16 + cb;
            float4 bv0 = *(const float4*)(bb + ni * 16 + cb);
            float4 bv1 = *(const float4*)(bb + ni * 16 + cb + 4);
            const float* sr = &sbuf[wid][r * 16 + cb];
            float4 o0, o1;
            o0.x = fmaxf(sr[0] + bv0.x, 0.f); o0.y = fmaxf(sr[1] + bv0.y, 0.f);
            o0.z = fmaxf(sr[2] + bv0.z, 0.f); o0.w = fmaxf(sr[3] + bv0.w, 0.f);
            o1.x = fmaxf(sr[4] + bv1.x, 0.f); o1.y = fmaxf(sr[5] + bv1.y, 0.f);
            o1.z = fmaxf(sr[6] + bv1.z, 0.f); o1.w = fmaxf(sr[7] + bv1.w, 0.f);
            *(float4*)(hr)     = o0;
            *(float4*)(hr + 4) = o1;
            __syncwarp();
        }
}

// ---------------- GEMM2: y[token] = (hmid @ w2 + b2) * prob -------------------
__global__ __launch_bounds__(256) void gemm2_wmma(const float* __restrict__ w2,
                                                  const float* __restrict__ b2,
                                                  float* __restrict__ y) {
    __shared__ __half sAh[128][ALD], sAl[128][ALD];
    __shared__ __half sBh[32][BLD], sBl[32][BLD];
    __shared__ __align__(32) float sbuf[8][256];

    int e = blockIdx.z, m0 = blockIdx.y * 128, n0 = blockIdx.x * 128;
    int cnt = g_count[e];
    if (m0 >= cnt) return;
    int tid = threadIdx.x, wid = tid >> 5, lane = tid & 31;
    int wm = (wid >> 2) * 64, wn = (wid & 3) * 32;

    wmma::fragment<wmma::accumulator, 16, 16, 16, float> acc[4][2];
#pragma unroll
    for (int mi = 0; mi < 4; mi++)
#pragma unroll
        for (int ni = 0; ni < 2; ni++) wmma::fill_fragment(acc[mi][ni], 0.f);

    fp16_mainloop<F_FF>(sAh, sAl, sBh, sBl,
        g_hmid + (size_t)(e * CAP + m0) * F_FF, F_FF,
        w2 + (size_t)e * F_FF * D_MODEL + n0, D_MODEL,
        acc, wm, wn);

    const float* bb = b2 + e * D_MODEL + n0 + wn;
    int r = lane >> 1, cb = (lane & 1) * 8;
#pragma unroll
    for (int mi = 0; mi < 4; mi++)
#pragma unroll
        for (int ni = 0; ni < 2; ni++) {
            wmma::store_matrix_sync(&sbuf[wid][0], acc[mi][ni], 16, wmma::mem_row_major);
            __syncwarp();
            int row = m0 + wm + mi * 16 + r;
            if (row < cnt) {
                int t = g_slot_token[e * CAP + row];
                float p = g_slot_prob[e * CAP + row];
                float* yr = y + (size_t)t * D_MODEL + n0 + wn + ni * 16 + cb;
                float4 bv0 = *(const float4*)(bb + ni * 16 + cb);
                float4 bv1 = *(const float4*)(bb + ni * 16 + cb + 4);
                const float* sr = &sbuf[wid][r * 16 + cb];
                float4 o0, o1;
                o0.x = (sr[0] + bv0.x) * p; o0.y = (sr[1] + bv0.y) * p;
                o0.z = (sr[2] + bv0.z) * p; o0.w = (sr[3] + bv0.w) * p;
                o1.x = (sr[4] + bv1.x) * p; o1.y = (sr[5] + bv1.y) * p;
                o1.z = (sr[6] + bv1.z) * p; o1.w = (sr[7] + bv1.w) * p;
                *(float4*)(yr)     = o0;
                *(float4*)(yr + 4) = o1;
            }
            __syncwarp();
        }
}

// ---------------- launch -------------------------------------------------------
extern "C" void kernel_launch(void* const* d_in, const int* in_sizes, int n_in,
                              void* d_out, int out_size) {
    const float* h      = (const float*)d_in[0];
    const float* gate_w = (const float*)d_in[1];
    const float* gate_b = (const float*)d_in[2];
    const float* w1     = (const float*)d_in[3];
    const float* b1     = (const float*)d_in[4];
    const float* w2     = (const float*)d_in[5];
    const float* b2     = (const float*)d_in[6];
    float* out = (float*)d_out;

    int n4 = out_size / 4;
    zero_kernel<<<(n4 + 255) / 256, 256>>>((float4*)out, n4);
    gate_kernel<<<T_TOKENS / 8, 256>>>(h, gate_w, gate_b);
    scan_kernel<<<1, 1024>>>();
    dispatch_kernel<<<E_EXPERTS * CAP / 4, 256>>>(h);
    gemm1_wmma<<<dim3(F_FF / 128, CAP / 128, E_EXPERTS), 256>>>(w1, b1);
    gemm2_wmma<<<dim3(D_MODEL / 128, CAP / 128, E_EXPERTS), 256>>>(w2, b2, out);
}

// round 16
// speedup vs baseline: 3.1714x; 1.0075x over previous
#include <cuda_runtime.h>
#include <cuda_fp16.h>
#include <mma.h>
#include <math.h>
#include <stdint.h>

using namespace nvcuda;

#define T_TOKENS 65536
#define D_MODEL  256
#define E_EXPERTS 8
#define F_FF     1024
#define CAP      10240

// ---------------- scratch (ONLY proven globals) -------------------------------
__device__ __align__(128) float g_buf[(size_t)E_EXPERTS * CAP * D_MODEL];
__device__ __align__(128) float g_hmid[(size_t)E_EXPERTS * CAP * F_FF];  // holds packed u32(half hi, half lo)
__device__ int   g_idx[T_TOKENS];
__device__ float g_prb[T_TOKENS];
__device__ int   g_slot_token[E_EXPERTS * CAP];
__device__ float g_slot_prob[E_EXPERTS * CAP];
__device__ int   g_count[E_EXPERTS];

// pack 2 floats -> half2 hi (returned) + half2 lo (out param)
__device__ __forceinline__ uint32_t packh2(float v0, float v1, uint32_t& lo) {
    __half2 hh = __float22half2_rn(make_float2(v0, v1));
    float2 bk = __half22float2(hh);
    __half2 ll = __float22half2_rn(make_float2(v0 - bk.x, v1 - bk.y));
    lo = *(uint32_t*)&ll;
    return *(uint32_t*)&hh;
}
// pack ONE float -> u32 = (half hi, half lo)
__device__ __forceinline__ uint32_t packv(float v) {
    __half h = __float2half_rn(v);
    __half l = __float2half_rn(v - __half2float(h));
    __half2 p = __halves2half2(h, l);
    return *(uint32_t*)&p;
}
// separate two packed values (h0,l0),(h1,l1) -> (h0,h1) and (l0,l1)
__device__ __forceinline__ void sep2(uint32_t x0, uint32_t x1, uint32_t& h, uint32_t& l) {
    h = __byte_perm(x0, x1, 0x5410);
    l = __byte_perm(x0, x1, 0x7632);
}

// SMEM strides (in halfs)
#define ALD 40
#define BLD 136

// ---------------- prep kernels (verbatim from passing rounds) -----------------
__global__ void zero_kernel(float4* __restrict__ out, int n4) {
    int i = blockIdx.x * blockDim.x + threadIdx.x;
    if (i < n4) out[i] = make_float4(0.f, 0.f, 0.f, 0.f);
}

__global__ void gate_kernel(const float* __restrict__ x,
                            const float* __restrict__ gw,
                            const float* __restrict__ gb) {
    __shared__ float s_gw[D_MODEL * E_EXPERTS];
    int tid = threadIdx.x;
    for (int i = tid; i < D_MODEL * E_EXPERTS; i += 256) s_gw[i] = gw[i];
    __syncthreads();
    int warp = tid >> 5, lane = tid & 31;
    int t = blockIdx.x * 8 + warp;
    const float* xr = x + (size_t)t * D_MODEL;
    float acc[E_EXPERTS];
#pragma unroll
    for (int e = 0; e < E_EXPERTS; e++) acc[e] = 0.f;
#pragma unroll
    for (int j = 0; j < 8; j++) {
        int d = j * 32 + lane;
        float xv = xr[d];
#pragma unroll
        for (int e = 0; e < E_EXPERTS; e++) acc[e] += xv * s_gw[d * E_EXPERTS + e];
    }
#pragma unroll
    for (int o = 16; o > 0; o >>= 1)
#pragma unroll
        for (int e = 0; e < E_EXPERTS; e++)
            acc[e] += __shfl_xor_sync(0xffffffffu, acc[e], o);
    if (lane == 0) {
        float lg[E_EXPERTS], m = -INFINITY; int am = 0;
#pragma unroll
        for (int e = 0; e < E_EXPERTS; e++) {
            lg[e] = acc[e] + gb[e];
            if (lg[e] > m) { m = lg[e]; am = e; }
        }
        float s = 0.f;
#pragma unroll
        for (int e = 0; e < E_EXPERTS; e++) s += expf(lg[e] - m);
        g_idx[t] = am;
        g_prb[t] = 1.0f / s;
    }
}

__global__ void scan_kernel() {
    __shared__ int s[1024][E_EXPERTS];
    int tid = threadIdx.x;
    int base = tid * (T_TOKENS / 1024);
    int cnt[E_EXPERTS];
#pragma unroll
    for (int e = 0; e < E_EXPERTS; e++) cnt[e] = 0;
    for (int i = 0; i < T_TOKENS / 1024; i++) cnt[g_idx[base + i]]++;
#pragma unroll
    for (int e = 0; e < E_EXPERTS; e++) s[tid][e] = cnt[e];
    __syncthreads();
    for (int off = 1; off < 1024; off <<= 1) {
        int v[E_EXPERTS];
        if (tid >= off)
#pragma unroll
            for (int e = 0; e < E_EXPERTS; e++) v[e] = s[tid - off][e];
        __syncthreads();
        if (tid >= off)
#pragma unroll
            for (int e = 0; e < E_EXPERTS; e++) s[tid][e] += v[e];
        __syncthreads();
    }
    int run[E_EXPERTS];
#pragma unroll
    for (int e = 0; e < E_EXPERTS; e++) run[e] = s[tid][e] - cnt[e];
    if (tid == 1023)
#pragma unroll
        for (int e = 0; e < E_EXPERTS; e++) g_count[e] = min(s[1023][e], CAP);
    for (int i = 0; i < T_TOKENS / 1024; i++) {
        int t = base + i;
        int e = g_idx[t];
        int pos = run[e]++;
        if (pos < CAP) {
            int slot = e * CAP + pos;
            g_slot_token[slot] = t;
            g_slot_prob[slot]  = g_prb[t];
        }
    }
}

__global__ void dispatch_kernel(const float* __restrict__ x) {
    int slot = blockIdx.x * 4 + (threadIdx.x >> 6);
    int e = slot / CAP, c = slot % CAP;
    if (c >= g_count[e]) return;
    int t = g_slot_token[slot];
    int i = threadIdx.x & 63;
    const float4* src = (const float4*)(x + (size_t)t * D_MODEL);
    float4* dst = (float4*)(g_buf + (size_t)slot * D_MODEL);
    dst[i] = src[i];
}

// ---------------- mainloop A-variant 1: fp32 A (gemm1) ------------------------
template <int KTOT>
__device__ __forceinline__ void fp16_mainloop_f32A(
        __half (*sAh)[ALD], __half (*sAl)[ALD],
        __half (*sBh)[BLD], __half (*sBl)[BLD],
        const float* __restrict__ A, int astr,
        const float* __restrict__ B, int bstr,
        wmma::fragment<wmma::accumulator, 16, 16, 16, float> acc[4][2],
        int wm, int wn) {
    int tid = threadIdx.x;
    int arow = tid >> 1, acol = (tid & 1) * 16;
    int brow = tid >> 3, bcol = (tid & 7) * 16;

    float4 pa[4], pb[4];
    auto ldchunk = [&](int k0) {
        const float* Ap = A + (size_t)arow * astr + k0 + acol;
        pa[0] = *(const float4*)(Ap);
        pa[1] = *(const float4*)(Ap + 4);
        pa[2] = *(const float4*)(Ap + 8);
        pa[3] = *(const float4*)(Ap + 12);
        const float* Bp = B + (size_t)(k0 + brow) * bstr + bcol;
        pb[0] = *(const float4*)(Bp);
        pb[1] = *(const float4*)(Bp + 4);
        pb[2] = *(const float4*)(Bp + 8);
        pb[3] = *(const float4*)(Bp + 12);
    };

    ldchunk(0);

#pragma unroll 1
    for (int k0 = 0; k0 < KTOT; k0 += 32) {
        {
            uint4 h0, l0, h1, l1;
            h0.x = packh2(pa[0].x, pa[0].y, l0.x); h0.y = packh2(pa[0].z, pa[0].w, l0.y);
            h0.z = packh2(pa[1].x, pa[1].y, l0.z); h0.w = packh2(pa[1].z, pa[1].w, l0.w);
            h1.x = packh2(pa[2].x, pa[2].y, l1.x); h1.y = packh2(pa[2].z, pa[2].w, l1.y);
            h1.z = packh2(pa[3].x, pa[3].y, l1.z); h1.w = packh2(pa[3].z, pa[3].w, l1.w);
            *(uint4*)(&sAh[arow][acol])     = h0;
            *(uint4*)(&sAh[arow][acol + 8]) = h1;
            *(uint4*)(&sAl[arow][acol])     = l0;
            *(uint4*)(&sAl[arow][acol + 8]) = l1;
        }
        {
            uint4 h0, l0, h1, l1;
            h0.x = packh2(pb[0].x, pb[0].y, l0.x); h0.y = packh2(pb[0].z, pb[0].w, l0.y);
            h0.z = packh2(pb[1].x, pb[1].y, l0.z); h0.w = packh2(pb[1].z, pb[1].w, l0.w);
            h1.x = packh2(pb[2].x, pb[2].y, l1.x); h1.y = packh2(pb[2].z, pb[2].w, l1.y);
            h1.z = packh2(pb[3].x, pb[3].y, l1.z); h1.w = packh2(pb[3].z, pb[3].w, l1.w);
            *(uint4*)(&sBh[brow][bcol])     = h0;
            *(uint4*)(&sBh[brow][bcol + 8]) = h1;
            *(uint4*)(&sBl[brow][bcol])     = l0;
            *(uint4*)(&sBl[brow][bcol + 8]) = l1;
        }
        __syncthreads();
        if (k0 + 32 < KTOT) ldchunk(k0 + 32);

#pragma unroll
        for (int ks = 0; ks < 2; ks++) {
            wmma::fragment<wmma::matrix_a, 16, 16, 16, __half, wmma::row_major> ah[4], al[4];
            wmma::fragment<wmma::matrix_b, 16, 16, 16, __half, wmma::row_major> bh[2], bl[2];
#pragma unroll
            for (int mi = 0; mi < 4; mi++) {
                wmma::load_matrix_sync(ah[mi], &sAh[wm + mi * 16][ks * 16], ALD);
                wmma::load_matrix_sync(al[mi], &sAl[wm + mi * 16][ks * 16], ALD);
            }
#pragma unroll
            for (int ni = 0; ni < 2; ni++) {
                wmma::load_matrix_sync(bh[ni], &sBh[ks * 16][wn + ni * 16], BLD);
                wmma::load_matrix_sync(bl[ni], &sBl[ks * 16][wn + ni * 16], BLD);
            }
#pragma unroll
            for (int mi = 0; mi < 4; mi++)
#pragma unroll
                for (int ni = 0; ni < 2; ni++) {
                    wmma::mma_sync(acc[mi][ni], ah[mi], bh[ni], acc[mi][ni]);
                    wmma::mma_sync(acc[mi][ni], ah[mi], bl[ni], acc[mi][ni]);
                    wmma::mma_sync(acc[mi][ni], al[mi], bh[ni], acc[mi][ni]);
                }
        }
        __syncthreads();
    }
}

// ---------------- mainloop A-variant 2: packed-u32 A (gemm2) ------------------
template <int KTOT>
__device__ __forceinline__ void fp16_mainloop_packA(
        __half (*sAh)[ALD], __half (*sAl)[ALD],
        __half (*sBh)[BLD], __half (*sBl)[BLD],
        const uint32_t* __restrict__ A, int astr,
        const float* __restrict__ B, int bstr,
        wmma::fragment<wmma::accumulator, 16, 16, 16, float> acc[4][2],
        int wm, int wn) {
    int tid = threadIdx.x;
    int arow = tid >> 1, acol = (tid & 1) * 16;
    int brow = tid >> 3, bcol = (tid & 7) * 16;

    uint4 pa[4];
    float4 pb[4];
    auto ldchunk = [&](int k0) {
        const uint32_t* Ap = A + (size_t)arow * astr + k0 + acol;
        pa[0] = *(const uint4*)(Ap);
        pa[1] = *(const uint4*)(Ap + 4);
        pa[2] = *(const uint4*)(Ap + 8);
        pa[3] = *(const uint4*)(Ap + 12);
        const float* Bp = B + (size_t)(k0 + brow) * bstr + bcol;
        pb[0] = *(const float4*)(Bp);
        pb[1] = *(const float4*)(Bp + 4);
        pb[2] = *(const float4*)(Bp + 8);
        pb[3] = *(const float4*)(Bp + 12);
    };

    ldchunk(0);

#pragma unroll 1
    for (int k0 = 0; k0 < KTOT; k0 += 32) {
        {
            uint4 h0, l0, h1, l1;
            sep2(pa[0].x, pa[0].y, h0.x, l0.x); sep2(pa[0].z, pa[0].w, h0.y, l0.y);
            sep2(pa[1].x, pa[1].y, h0.z, l0.z); sep2(pa[1].z, pa[1].w, h0.w, l0.w);
            sep2(pa[2].x, pa[2].y, h1.x, l1.x); sep2(pa[2].z, pa[2].w, h1.y, l1.y);
            sep2(pa[3].x, pa[3].y, h1.z, l1.z); sep2(pa[3].z, pa[3].w, h1.w, l1.w);
            *(uint4*)(&sAh[arow][acol])     = h0;
            *(uint4*)(&sAh[arow][acol + 8]) = h1;
            *(uint4*)(&sAl[arow][acol])     = l0;
            *(uint4*)(&sAl[arow][acol + 8]) = l1;
        }
        {
            uint4 h0, l0, h1, l1;
            h0.x = packh2(pb[0].x, pb[0].y, l0.x); h0.y = packh2(pb[0].z, pb[0].w, l0.y);
            h0.z = packh2(pb[1].x, pb[1].y, l0.z); h0.w = packh2(pb[1].z, pb[1].w, l0.w);
            h1.x = packh2(pb[2].x, pb[2].y, l1.x); h1.y = packh2(pb[2].z, pb[2].w, l1.y);
            h1.z = packh2(pb[3].x, pb[3].y, l1.z); h1.w = packh2(pb[3].z, pb[3].w, l1.w);
            *(uint4*)(&sBh[brow][bcol])     = h0;
            *(uint4*)(&sBh[brow][bcol + 8]) = h1;
            *(uint4*)(&sBl[brow][bcol])     = l0;
            *(uint4*)(&sBl[brow][bcol + 8]) = l1;
        }
        __syncthreads();
        if (k0 + 32 < KTOT) ldchunk(k0 + 32);

#pragma unroll
        for (int ks = 0; ks < 2; ks++) {
            wmma::fragment<wmma::matrix_a, 16, 16, 16, __half, wmma::row_major> ah[4], al[4];
            wmma::fragment<wmma::matrix_b, 16, 16, 16, __half, wmma::row_major> bh[2], bl[2];
#pragma unroll
            for (int mi = 0; mi < 4; mi++) {
                wmma::load_matrix_sync(ah[mi], &sAh[wm + mi * 16][ks * 16], ALD);
                wmma::load_matrix_sync(al[mi], &sAl[wm + mi * 16][ks * 16], ALD);
            }
#pragma unroll
            for (int ni = 0; ni < 2; ni++) {
                wmma::load_matrix_sync(bh[ni], &sBh[ks * 16][wn + ni * 16], BLD);
                wmma::load_matrix_sync(bl[ni], &sBl[ks * 16][wn + ni * 16], BLD);
            }
#pragma unroll
            for (int mi = 0; mi < 4; mi++)
#pragma unroll
                for (int ni = 0; ni < 2; ni++) {
                    wmma::mma_sync(acc[mi][ni], ah[mi], bh[ni], acc[mi][ni]);
                    wmma::mma_sync(acc[mi][ni], ah[mi], bl[ni], acc[mi][ni]);
                    wmma::mma_sync(acc[mi][ni], al[mi], bh[ni], acc[mi][ni]);
                }
        }
        __syncthreads();
    }
}

// ---------------- GEMM1: hmid = relu(buf @ w1 + b1), PACKED u32 out -----------
__global__ __launch_bounds__(256) void gemm1_wmma(const float* __restrict__ w1,
                                                  const float* __restrict__ b1) {
    __shared__ __half sAh[128][ALD], sAl[128][ALD];
    __shared__ __half sBh[32][BLD], sBl[32][BLD];
    __shared__ __align__(32) float sbuf[8][256];

    int e = blockIdx.z, m0 = blockIdx.y * 128, n0 = blockIdx.x * 128;
    if (m0 >= g_count[e]) return;
    int tid = threadIdx.x, wid = tid >> 5, lane = tid & 31;
    int wm = (wid >> 2) * 64, wn = (wid & 3) * 32;

    wmma::fragment<wmma::accumulator, 16, 16, 16, float> acc[4][2];
#pragma unroll
    for (int mi = 0; mi < 4; mi++)
#pragma unroll
        for (int ni = 0; ni < 2; ni++) wmma::fill_fragment(acc[mi][ni], 0.f);

    fp16_mainloop_f32A<D_MODEL>(sAh, sAl, sBh, sBl,
        g_buf + (size_t)(e * CAP + m0) * D_MODEL, D_MODEL,
        w1 + (size_t)e * D_MODEL * F_FF + n0, F_FF,
        acc, wm, wn);

    const float* bb = b1 + e * F_FF + n0 + wn;
    int r = lane >> 1, cb = (lane & 1) * 8;
    uint32_t* Hm = (uint32_t*)g_hmid;
#pragma unroll
    for (int mi = 0; mi < 4; mi++)
#pragma unroll
        for (int ni = 0; ni < 2; ni++) {
            wmma::store_matrix_sync(&sbuf[wid][0], acc[mi][ni], 16, wmma::mem_row_major);
            __syncwarp();
            uint32_t* hr = Hm + (size_t)(e * CAP + m0 + wm + mi * 16 + r) * F_FF
                        + n0 + wn + ni * 16 + cb;
            float4 bv0 = *(const float4*)(bb + ni * 16 + cb);
            float4 bv1 = *(const float4*)(bb + ni * 16 + cb + 4);
            const float* sr = &sbuf[wid][r * 16 + cb];
            uint4 o0, o1;
            o0.x = packv(fmaxf(sr[0] + bv0.x, 0.f));
            o0.y = packv(fmaxf(sr[1] + bv0.y, 0.f));
            o0.z = packv(fmaxf(sr[2] + bv0.z, 0.f));
            o0.w = packv(fmaxf(sr[3] + bv0.w, 0.f));
            o1.x = packv(fmaxf(sr[4] + bv1.x, 0.f));
            o1.y = packv(fmaxf(sr[5] + bv1.y, 0.f));
            o1.z = packv(fmaxf(sr[6] + bv1.z, 0.f));
            o1.w = packv(fmaxf(sr[7] + bv1.w, 0.f));
            *(uint4*)(hr)     = o0;
            *(uint4*)(hr + 4) = o1;
            __syncwarp();
        }
}

// ---------------- GEMM2: y[token] = (hmid @ w2 + b2) * prob -------------------
__global__ __launch_bounds__(256) void gemm2_wmma(const float* __restrict__ w2,
                                                  const float* __restrict__ b2,
                                                  float* __restrict__ y) {
    __shared__ __half sAh[128][ALD], sAl[128][ALD];
    __shared__ __half sBh[32][BLD], sBl[32][BLD];
    __shared__ __align__(32) float sbuf[8][256];

    int e = blockIdx.z, m0 = blockIdx.y * 128, n0 = blockIdx.x * 128;
    int cnt = g_count[e];
    if (m0 >= cnt) return;
    int tid = threadIdx.x, wid = tid >> 5, lane = tid & 31;
    int wm = (wid >> 2) * 64, wn = (wid & 3) * 32;

    wmma::fragment<wmma::accumulator, 16, 16, 16, float> acc[4][2];
#pragma unroll
    for (int mi = 0; mi < 4; mi++)
#pragma unroll
        for (int ni = 0; ni < 2; ni++) wmma::fill_fragment(acc[mi][ni], 0.f);

    fp16_mainloop_packA<F_FF>(sAh, sAl, sBh, sBl,
        (const uint32_t*)g_hmid + (size_t)(e * CAP + m0) * F_FF, F_FF,
        w2 + (size_t)e * F_FF * D_MODEL + n0, D_MODEL,
        acc, wm, wn);

    const float* bb = b2 + e * D_MODEL + n0 + wn;
    int r = lane >> 1, cb = (lane & 1) * 8;
#pragma unroll
    for (int mi = 0; mi < 4; mi++)
#pragma unroll
        for (int ni = 0; ni < 2; ni++) {
            wmma::store_matrix_sync(&sbuf[wid][0], acc[mi][ni], 16, wmma::mem_row_major);
            __syncwarp();
            int row = m0 + wm + mi * 16 + r;
            if (row < cnt) {
                int t = g_slot_token[e * CAP + row];
                float p = g_slot_prob[e * CAP + row];
                float* yr = y + (size_t)t * D_MODEL + n0 + wn + ni * 16 + cb;
                float4 bv0 = *(const float4*)(bb + ni * 16 + cb);
                float4 bv1 = *(const float4*)(bb + ni * 16 + cb + 4);
                const float* sr = &sbuf[wid][r * 16 + cb];
                float4 o0, o1;
                o0.x = (sr[0] + bv0.x) * p; o0.y = (sr[1] + bv0.y) * p;
                o0.z = (sr[2] + bv0.z) * p; o0.w = (sr[3] + bv0.w) * p;
                o1.x = (sr[4] + bv1.x) * p; o1.y = (sr[5] + bv1.y) * p;
                o1.z = (sr[6] + bv1.z) * p; o1.w = (sr[7] + bv1.w) * p;
                *(float4*)(yr)     = o0;
                *(float4*)(yr + 4) = o1;
            }
            __syncwarp();
        }
}

// ---------------- launch -------------------------------------------------------
extern "C" void kernel_launch(void* const* d_in, const int* in_sizes, int n_in,
                              void* d_out, int out_size) {
    const float* h      = (const float*)d_in[0];
    const float* gate_w = (const float*)d_in[1];
    const float* gate_b = (const float*)d_in[2];
    const float* w1     = (const float*)d_in[3];
    const float* b1     = (const float*)d_in[4];
    const float* w2     = (const float*)d_in[5];
    const float* b2     = (const float*)d_in[6];
    float* out = (float*)d_out;

    int n4 = out_size / 4;
    zero_kernel<<<(n4 + 255) / 256, 256>>>((float4*)out, n4);
    gate_kernel<<<T_TOKENS / 8, 256>>>(h, gate_w, gate_b);
    scan_kernel<<<1, 1024>>>();
    dispatch_kernel<<<E_EXPERTS * CAP / 4, 256>>>(h);
    gemm1_wmma<<<dim3(F_FF / 128, CAP / 128, E_EXPERTS), 256>>>(w1, b1);
    gemm2_wmma<<<dim3(D_MODEL / 128, CAP / 128, E_EXPERTS), 256>>>(w2, b2, out);
}

// round 17
// speedup vs baseline: 3.4408x; 1.0849x over previous
#include <cuda_runtime.h>
#include <cuda_fp16.h>
#include <mma.h>
#include <math.h>
#include <stdint.h>

using namespace nvcuda;

#define T_TOKENS 65536
#define D_MODEL  256
#define E_EXPERTS 8
#define F_FF     1024
#define CAP      10240

// ---------------- scratch (proven globals) -------------------------------------
__device__ __align__(128) float g_buf[(size_t)E_EXPERTS * CAP * D_MODEL];
__device__ __align__(128) float g_hmid[(size_t)E_EXPERTS * CAP * F_FF];  // packed u32(half hi, half lo)
__device__ int   g_idx[T_TOKENS];
__device__ float g_prb[T_TOKENS];
__device__ int   g_slot_token[E_EXPERTS * CAP];
__device__ float g_slot_prob[E_EXPERTS * CAP];
__device__ int   g_count[E_EXPERTS];

__device__ __forceinline__ uint32_t packh2(float v0, float v1, uint32_t& lo) {
    __half2 hh = __float22half2_rn(make_float2(v0, v1));
    float2 bk = __half22float2(hh);
    __half2 ll = __float22half2_rn(make_float2(v0 - bk.x, v1 - bk.y));
    lo = *(uint32_t*)&ll;
    return *(uint32_t*)&hh;
}
__device__ __forceinline__ uint32_t packv(float v) {
    __half h = __float2half_rn(v);
    __half l = __float2half_rn(v - __half2float(h));
    __half2 p = __halves2half2(h, l);
    return *(uint32_t*)&p;
}
__device__ __forceinline__ void sep2(uint32_t x0, uint32_t x1, uint32_t& h, uint32_t& l) {
    h = __byte_perm(x0, x1, 0x5410);
    l = __byte_perm(x0, x1, 0x7632);
}

// SMEM layout: 2 stages, K-chunk 16
#define ALD 24                      // halfs per A row (16 + 8 pad) -> 48B rows
#define BLD 136                     // halfs per B row (128 + 8 pad) -> 272B rows
#define A_SZ (128 * ALD * 2)        // 6144 B
#define B_SZ (16 * BLD * 2)         // 4352 B
#define STAGE_SZ (2 * A_SZ + 2 * B_SZ)  // 20992 B
#define SMEM_TOT (2 * STAGE_SZ)         // 41984 B

// ---------------- prep kernels (verbatim, proven) -------------------------------
__global__ void zero_kernel(float4* __restrict__ out, int n4) {
    int i = blockIdx.x * blockDim.x + threadIdx.x;
    if (i < n4) out[i] = make_float4(0.f, 0.f, 0.f, 0.f);
}

__global__ void gate_kernel(const float* __restrict__ x,
                            const float* __restrict__ gw,
                            const float* __restrict__ gb) {
    __shared__ float s_gw[D_MODEL * E_EXPERTS];
    int tid = threadIdx.x;
    for (int i = tid; i < D_MODEL * E_EXPERTS; i += 256) s_gw[i] = gw[i];
    __syncthreads();
    int warp = tid >> 5, lane = tid & 31;
    int t = blockIdx.x * 8 + warp;
    const float* xr = x + (size_t)t * D_MODEL;
    float acc[E_EXPERTS];
#pragma unroll
    for (int e = 0; e < E_EXPERTS; e++) acc[e] = 0.f;
#pragma unroll
    for (int j = 0; j < 8; j++) {
        int d = j * 32 + lane;
        float xv = xr[d];
#pragma unroll
        for (int e = 0; e < E_EXPERTS; e++) acc[e] += xv * s_gw[d * E_EXPERTS + e];
    }
#pragma unroll
    for (int o = 16; o > 0; o >>= 1)
#pragma unroll
        for (int e = 0; e < E_EXPERTS; e++)
            acc[e] += __shfl_xor_sync(0xffffffffu, acc[e], o);
    if (lane == 0) {
        float lg[E_EXPERTS], m = -INFINITY; int am = 0;
#pragma unroll
        for (int e = 0; e < E_EXPERTS; e++) {
            lg[e] = acc[e] + gb[e];
            if (lg[e] > m) { m = lg[e]; am = e; }
        }
        float s = 0.f;
#pragma unroll
        for (int e = 0; e < E_EXPERTS; e++) s += expf(lg[e] - m);
        g_idx[t] = am;
        g_prb[t] = 1.0f / s;
    }
}

__global__ void scan_kernel() {
    __shared__ int s[1024][E_EXPERTS];
    int tid = threadIdx.x;
    int base = tid * (T_TOKENS / 1024);
    int cnt[E_EXPERTS];
#pragma unroll
    for (int e = 0; e < E_EXPERTS; e++) cnt[e] = 0;
    for (int i = 0; i < T_TOKENS / 1024; i++) cnt[g_idx[base + i]]++;
#pragma unroll
    for (int e = 0; e < E_EXPERTS; e++) s[tid][e] = cnt[e];
    __syncthreads();
    for (int off = 1; off < 1024; off <<= 1) {
        int v[E_EXPERTS];
        if (tid >= off)
#pragma unroll
            for (int e = 0; e < E_EXPERTS; e++) v[e] = s[tid - off][e];
        __syncthreads();
        if (tid >= off)
#pragma unroll
            for (int e = 0; e < E_EXPERTS; e++) s[tid][e] += v[e];
        __syncthreads();
    }
    int run[E_EXPERTS];
#pragma unroll
    for (int e = 0; e < E_EXPERTS; e++) run[e] = s[tid][e] - cnt[e];
    if (tid == 1023)
#pragma unroll
        for (int e = 0; e < E_EXPERTS; e++) g_count[e] = min(s[1023][e], CAP);
    for (int i = 0; i < T_TOKENS / 1024; i++) {
        int t = base + i;
        int e = g_idx[t];
        int pos = run[e]++;
        if (pos < CAP) {
            int slot = e * CAP + pos;
            g_slot_token[slot] = t;
            g_slot_prob[slot]  = g_prb[t];
        }
    }
}

__global__ void dispatch_kernel(const float* __restrict__ x) {
    int slot = blockIdx.x * 4 + (threadIdx.x >> 6);
    int e = slot / CAP, c = slot % CAP;
    if (c >= g_count[e]) return;
    int t = g_slot_token[slot];
    int i = threadIdx.x & 63;
    const float4* src = (const float4*)(x + (size_t)t * D_MODEL);
    float4* dst = (float4*)(g_buf + (size_t)slot * D_MODEL);
    dst[i] = src[i];
}

// ---------------- double-buffered fp16 3-term mainloops ------------------------
// Tile 128x128, 8 warps (2m x 4n), warp 64x32, K-chunk 16, 2 stages, 1 sync/chunk.
struct StagePtrs {
    __half (*Ah)[ALD]; __half (*Al)[ALD];
    __half (*Bh)[BLD]; __half (*Bl)[BLD];
};
__device__ __forceinline__ StagePtrs stage_ptrs(char* sm, int s) {
    char* b = sm + s * STAGE_SZ;
    StagePtrs p;
    p.Ah = (__half (*)[ALD])(b);
    p.Al = (__half (*)[ALD])(b + A_SZ);
    p.Bh = (__half (*)[BLD])(b + 2 * A_SZ);
    p.Bl = (__half (*)[BLD])(b + 2 * A_SZ + B_SZ);
    return p;
}

__device__ __forceinline__ void mma_stage(
        const StagePtrs& p,
        wmma::fragment<wmma::accumulator, 16, 16, 16, float> acc[4][2],
        int wm, int wn) {
    wmma::fragment<wmma::matrix_a, 16, 16, 16, __half, wmma::row_major> ah[4], al[4];
    wmma::fragment<wmma::matrix_b, 16, 16, 16, __half, wmma::row_major> bh[2], bl[2];
#pragma unroll
    for (int mi = 0; mi < 4; mi++) {
        wmma::load_matrix_sync(ah[mi], &p.Ah[wm + mi * 16][0], ALD);
        wmma::load_matrix_sync(al[mi], &p.Al[wm + mi * 16][0], ALD);
    }
#pragma unroll
    for (int ni = 0; ni < 2; ni++) {
        wmma::load_matrix_sync(bh[ni], &p.Bh[0][wn + ni * 16], BLD);
        wmma::load_matrix_sync(bl[ni], &p.Bl[0][wn + ni * 16], BLD);
    }
#pragma unroll
    for (int mi = 0; mi < 4; mi++)
#pragma unroll
        for (int ni = 0; ni < 2; ni++) {
            wmma::mma_sync(acc[mi][ni], ah[mi], bh[ni], acc[mi][ni]);
            wmma::mma_sync(acc[mi][ni], ah[mi], bl[ni], acc[mi][ni]);
            wmma::mma_sync(acc[mi][ni], al[mi], bh[ni], acc[mi][ni]);
        }
}

// GEMM1 mainloop: A fp32 (g_buf), B fp32 (w1)
template <int KTOT>
__device__ __forceinline__ void loop_f32A(char* sm,
        const float* __restrict__ A, int astr,
        const float* __restrict__ B, int bstr,
        wmma::fragment<wmma::accumulator, 16, 16, 16, float> acc[4][2],
        int wm, int wn) {
    constexpr int NC = KTOT / 16;
    int tid = threadIdx.x;
    int arow = tid >> 1, acol = (tid & 1) * 8;
    int brow = tid >> 4, bcol = (tid & 15) * 8;

    float4 pa0, pa1, pb0, pb1;
    auto ldg = [&](int c) {
        int k0 = c * 16;
        const float* Ap = A + (size_t)arow * astr + k0 + acol;
        pa0 = *(const float4*)(Ap);
        pa1 = *(const float4*)(Ap + 4);
        const float* Bp = B + (size_t)(k0 + brow) * bstr + bcol;
        pb0 = *(const float4*)(Bp);
        pb1 = *(const float4*)(Bp + 4);
    };
    auto cvst = [&](int s) {
        StagePtrs p = stage_ptrs(sm, s);
        uint4 h, l;
        h.x = packh2(pa0.x, pa0.y, l.x); h.y = packh2(pa0.z, pa0.w, l.y);
        h.z = packh2(pa1.x, pa1.y, l.z); h.w = packh2(pa1.z, pa1.w, l.w);
        *(uint4*)(&p.Ah[arow][acol]) = h;
        *(uint4*)(&p.Al[arow][acol]) = l;
        h.x = packh2(pb0.x, pb0.y, l.x); h.y = packh2(pb0.z, pb0.w, l.y);
        h.z = packh2(pb1.x, pb1.y, l.z); h.w = packh2(pb1.z, pb1.w, l.w);
        *(uint4*)(&p.Bh[brow][bcol]) = h;
        *(uint4*)(&p.Bl[brow][bcol]) = l;
    };

    ldg(0); cvst(0);
    if (NC > 1) ldg(1);
    __syncthreads();

#pragma unroll 1
    for (int c = 0; c < NC; c++) {
        int s = c & 1;
        if (c + 1 < NC) cvst(s ^ 1);      // regs hold chunk c+1
        if (c + 2 < NC) ldg(c + 2);       // regs freed, fetch c+2
        mma_stage(stage_ptrs(sm, s), acc, wm, wn);
        __syncthreads();
    }
}

// GEMM2 mainloop: A packed u32 (g_hmid), B fp32 (w2)
template <int KTOT>
__device__ __forceinline__ void loop_packA(char* sm,
        const uint32_t* __restrict__ A, int astr,
        const float* __restrict__ B, int bstr,
        wmma::fragment<wmma::accumulator, 16, 16, 16, float> acc[4][2],
        int wm, int wn) {
    constexpr int NC = KTOT / 16;
    int tid = threadIdx.x;
    int arow = tid >> 1, acol = (tid & 1) * 8;
    int brow = tid >> 4, bcol = (tid & 15) * 8;

    uint4 pa0, pa1;
    float4 pb0, pb1;
    auto ldg = [&](int c) {
        int k0 = c * 16;
        const uint32_t* Ap = A + (size_t)arow * astr + k0 + acol;
        pa0 = *(const uint4*)(Ap);
        pa1 = *(const uint4*)(Ap + 4);
        const float* Bp = B + (size_t)(k0 + brow) * bstr + bcol;
        pb0 = *(const float4*)(Bp);
        pb1 = *(const float4*)(Bp + 4);
    };
    auto cvst = [&](int s) {
        StagePtrs p = stage_ptrs(sm, s);
        uint4 h, l;
        sep2(pa0.x, pa0.y, h.x, l.x); sep2(pa0.z, pa0.w, h.y, l.y);
        sep2(pa1.x, pa1.y, h.z, l.z); sep2(pa1.z, pa1.w, h.w, l.w);
        *(uint4*)(&p.Ah[arow][acol]) = h;
        *(uint4*)(&p.Al[arow][acol]) = l;
        h.x = packh2(pb0.x, pb0.y, l.x); h.y = packh2(pb0.z, pb0.w, l.y);
        h.z = packh2(pb1.x, pb1.y, l.z); h.w = packh2(pb1.z, pb1.w, l.w);
        *(uint4*)(&p.Bh[brow][bcol]) = h;
        *(uint4*)(&p.Bl[brow][bcol]) = l;
    };

    ldg(0); cvst(0);
    if (NC > 1) ldg(1);
    __syncthreads();

#pragma unroll 1
    for (int c = 0; c < NC; c++) {
        int s = c & 1;
        if (c + 1 < NC) cvst(s ^ 1);
        if (c + 2 < NC) ldg(c + 2);
        mma_stage(stage_ptrs(sm, s), acc, wm, wn);
        __syncthreads();
    }
}

// ---------------- GEMM1: hmid = relu(buf @ w1 + b1), PACKED u32 out ------------
__global__ __launch_bounds__(256) void gemm1_wmma(const float* __restrict__ w1,
                                                  const float* __restrict__ b1) {
    __shared__ __align__(16) char sm[SMEM_TOT];
    int e = blockIdx.z, m0 = blockIdx.y * 128, n0 = blockIdx.x * 128;
    if (m0 >= g_count[e]) return;
    int tid = threadIdx.x, wid = tid >> 5, lane = tid & 31;
    int wm = (wid >> 2) * 64, wn = (wid & 3) * 32;

    wmma::fragment<wmma::accumulator, 16, 16, 16, float> acc[4][2];
#pragma unroll
    for (int mi = 0; mi < 4; mi++)
#pragma unroll
        for (int ni = 0; ni < 2; ni++) wmma::fill_fragment(acc[mi][ni], 0.f);

    loop_f32A<D_MODEL>(sm,
        g_buf + (size_t)(e * CAP + m0) * D_MODEL, D_MODEL,
        w1 + (size_t)e * D_MODEL * F_FF + n0, F_FF,
        acc, wm, wn);

    // epilogue scratch aliases stage 0 (all reads done; final sync in loop)
    float* sw = (float*)sm + wid * 256;
    const float* bb = b1 + e * F_FF + n0 + wn;
    int r = lane >> 1, cb = (lane & 1) * 8;
    uint32_t* Hm = (uint32_t*)g_hmid;
#pragma unroll
    for (int mi = 0; mi < 4; mi++)
#pragma unroll
        for (int ni = 0; ni < 2; ni++) {
            wmma::store_matrix_sync(sw, acc[mi][ni], 16, wmma::mem_row_major);
            __syncwarp();
            uint32_t* hr = Hm + (size_t)(e * CAP + m0 + wm + mi * 16 + r) * F_FF
                        + n0 + wn + ni * 16 + cb;
            float4 bv0 = *(const float4*)(bb + ni * 16 + cb);
            float4 bv1 = *(const float4*)(bb + ni * 16 + cb + 4);
            const float* sr = sw + r * 16 + cb;
            uint4 o0, o1;
            o0.x = packv(fmaxf(sr[0] + bv0.x, 0.f));
            o0.y = packv(fmaxf(sr[1] + bv0.y, 0.f));
            o0.z = packv(fmaxf(sr[2] + bv0.z, 0.f));
            o0.w = packv(fmaxf(sr[3] + bv0.w, 0.f));
            o1.x = packv(fmaxf(sr[4] + bv1.x, 0.f));
            o1.y = packv(fmaxf(sr[5] + bv1.y, 0.f));
            o1.z = packv(fmaxf(sr[6] + bv1.z, 0.f));
            o1.w = packv(fmaxf(sr[7] + bv1.w, 0.f));
            *(uint4*)(hr)     = o0;
            *(uint4*)(hr + 4) = o1;
            __syncwarp();
        }
}

// ---------------- GEMM2: y[token] = (hmid @ w2 + b2) * prob --------------------
__global__ __launch_bounds__(256) void gemm2_wmma(const float* __restrict__ w2,
                                                  const float* __restrict__ b2,
                                                  float* __restrict__ y) {
    __shared__ __align__(16) char sm[SMEM_TOT];
    int e = blockIdx.z, m0 = blockIdx.y * 128, n0 = blockIdx.x * 128;
    int cnt = g_count[e];
    if (m0 >= cnt) return;
    int tid = threadIdx.x, wid = tid >> 5, lane = tid & 31;
    int wm = (wid >> 2) * 64, wn = (wid & 3) * 32;

    wmma::fragment<wmma::accumulator, 16, 16, 16, float> acc[4][2];
#pragma unroll
    for (int mi = 0; mi < 4; mi++)
#pragma unroll
        for (int ni = 0; ni < 2; ni++) wmma::fill_fragment(acc[mi][ni], 0.f);

    loop_packA<F_FF>(sm,
        (const uint32_t*)g_hmid + (size_t)(e * CAP + m0) * F_FF, F_FF,
        w2 + (size_t)e * F_FF * D_MODEL + n0, D_MODEL,
        acc, wm, wn);

    float* sw = (float*)sm + wid * 256;
    const float* bb = b2 + e * D_MODEL + n0 + wn;
    int r = lane >> 1, cb = (lane & 1) * 8;
#pragma unroll
    for (int mi = 0; mi < 4; mi++)
#pragma unroll
        for (int ni = 0; ni < 2; ni++) {
            wmma::store_matrix_sync(sw, acc[mi][ni], 16, wmma::mem_row_major);
            __syncwarp();
            int row = m0 + wm + mi * 16 + r;
            if (row < cnt) {
                int t = g_slot_token[e * CAP + row];
                float p = g_slot_prob[e * CAP + row];
                float* yr = y + (size_t)t * D_MODEL + n0 + wn + ni * 16 + cb;
                float4 bv0 = *(const float4*)(bb + ni * 16 + cb);
                float4 bv1 = *(const float4*)(bb + ni * 16 + cb + 4);
                const float* sr = sw + r * 16 + cb;
                float4 o0, o1;
                o0.x = (sr[0] + bv0.x) * p; o0.y = (sr[1] + bv0.y) * p;
                o0.z = (sr[2] + bv0.z) * p; o0.w = (sr[3] + bv0.w) * p;
                o1.x = (sr[4] + bv1.x) * p; o1.y = (sr[5] + bv1.y) * p;
                o1.z = (sr[6] + bv1.z) * p; o1.w = (sr[7] + bv1.w) * p;
                *(float4*)(yr)     = o0;
                *(float4*)(yr + 4) = o1;
            }
            __syncwarp();
        }
}

// ---------------- launch ---------------------------------------------------------
extern "C" void kernel_launch(void* const* d_in, const int* in_sizes, int n_in,
                              void* d_out, int out_size) {
    const float* h      = (const float*)d_in[0];
    const float* gate_w = (const float*)d_in[1];
    const float* gate_b = (const float*)d_in[2];
    const float* w1     = (const float*)d_in[3];
    const float* b1     = (const float*)d_in[4];
    const float* w2     = (const float*)d_in[5];
    const float* b2     = (const float*)d_in[6];
    float* out = (float*)d_out;

    int n4 = out_size / 4;
    zero_kernel<<<(n4 + 255) / 256, 256>>>((float4*)out, n4);
    gate_kernel<<<T_TOKENS / 8, 256>>>(h, gate_w, gate_b);
    scan_kernel<<<1, 1024>>>();
    dispatch_kernel<<<E_EXPERTS * CAP / 4, 256>>>(h);
    gemm1_wmma<<<dim3(F_FF / 128, CAP / 128, E_EXPERTS), 256>>>(w1, b1);
    gemm2_wmma<<<dim3(D_MODEL / 128, CAP / 128, E_EXPERTS), 256>>>(b2 ? w2 : w2, b2, out);
}